// round 10
// baseline (speedup 1.0000x reference)
#include <cuda_runtime.h>
#include <math.h>
#include <stdint.h>

#define N_TOK   8192
#define NE      8192
#define EDIM    256
#define BATCH   8
#define HW      1024

#define MT      64                  // tokens per CTA (4 m16 tiles) -> 128 CTAs
#define NCH     32                  // chunks of 256 codes (32 ntiles)
#define SZ      16.0f               // z scale (int8)
#define SE      1048576.0f          // emb scale 2^20 (int8, saturating)
#define EPS_INT 4096                // quantized-dot epsilon (2.44e-4 unscaled, ~8-12 sigma)
#define BD_INIT (-2000000000)       // bestD init: BD_INIT - EPS_INT must not underflow!
#define CAP     32

#define CHUNK_SLOTS 4096            // 32 ntiles * 4 kpairs * 32 lanes (uint4), 64KB

typedef unsigned long long ull;

// ---- scratch (static device globals; no allocation) ----
__device__ __align__(16) float g_zf[N_TOK * EDIM];          // z [token][dim]
__device__ __align__(16) uint4 g_embF[NE / 8 * 4 * 32];     // emb int8 frags (2MB)
__device__ ull   g_cand[N_TOK * 2 * 4 * CAP];               // (dotBits<<32)|idx appends
__device__ ull   g_best[N_TOK];
__device__ float g_msePart[BATCH * 256];

__device__ __forceinline__ int q8(float x, float s) {
    int v = __float2int_rn(x * s);
    return v > 127 ? 127 : (v < -127 ? -127 : v);
}
__device__ __forceinline__ uint32_t q4(const float* p, float s) {
    int b0 = q8(p[0], s), b1 = q8(p[1], s), b2 = q8(p[2], s), b3 = q8(p[3], s);
    return (uint32_t)(b0 & 255) | ((uint32_t)(b1 & 255) << 8) |
           ((uint32_t)(b2 & 255) << 16) | ((uint32_t)(b3 & 255) << 24);
}
__device__ __forceinline__ void mma_s8(int* d, const uint4& a, uint32_t b0, uint32_t b1) {
    asm("mma.sync.aligned.m16n8k32.row.col.s32.s8.s8.s32 "
        "{%0,%1,%2,%3},{%4,%5,%6,%7},{%8,%9},{%0,%1,%2,%3};"
        : "+r"(d[0]), "+r"(d[1]), "+r"(d[2]), "+r"(d[3])
        : "r"(a.x), "r"(a.y), "r"(a.z), "r"(a.w), "r"(b0), "r"(b1));
}
__device__ __forceinline__ uint32_t smem_u32(const void* p) {
    uint32_t a;
    asm("{ .reg .u64 t; cvta.to.shared.u64 t, %1; cvt.u32.u64 %0, t; }" : "=r"(a) : "l"(p));
    return a;
}
__device__ __forceinline__ void cp16(uint32_t dst, const void* src) {
    asm volatile("cp.async.cg.shared.global [%0], [%1], 16;" :: "r"(dst), "l"(src) : "memory");
}

// ------------------------------------------------------------------
// K1: NCHW -> [token][dim] transpose  (+ init g_best)
// ------------------------------------------------------------------
__global__ void k_transpose(const float* __restrict__ z) {
    __shared__ float tile[32][33];
    const int b = blockIdx.z;
    const int hwBase = blockIdx.x * 32;
    const int cBase  = blockIdx.y * 32;
    const int tx = threadIdx.x, ty = threadIdx.y;
    const int bid  = (blockIdx.z * gridDim.y + blockIdx.y) * gridDim.x + blockIdx.x;
    const int tlin = bid * 256 + ty * 32 + tx;
    if (tlin < N_TOK) g_best[tlin] = ~0ULL;
#pragma unroll
    for (int j = 0; j < 4; j++) {
        int c = cBase + ty + 8 * j;
        tile[ty + 8 * j][tx] = z[(b * EDIM + c) * HW + hwBase + tx];
    }
    __syncthreads();
#pragma unroll
    for (int j = 0; j < 4; j++) {
        int hw = hwBase + ty + 8 * j;
        g_zf[(b * HW + hw) * EDIM + cBase + tx] = tile[tx][ty + 8 * j];
    }
}

// ------------------------------------------------------------------
// K1b: emb -> int8 fragment layout (m16n8k32 B frags, 2 ksteps/uint4).
// slot = (ntile*4 + kpair)*32 + lane; n = ntile*8 + lane/4; kb = kpair*64 + (lane%4)*4
// ------------------------------------------------------------------
__global__ void k_embfrag(const float* __restrict__ emb) {
    int slot = blockIdx.x * 256 + threadIdx.x;      // 0 .. 131071
    int lane  = slot & 31;
    int kp    = (slot >> 5) & 3;
    int ntile = slot >> 7;
    int n  = ntile * 8 + (lane >> 2);
    int kb = kp * 64 + (lane & 3) * 4;
    const float* e = emb + n * EDIM + kb;
    uint4 v;
    v.x = q4(e,      SE);
    v.y = q4(e + 16, SE);
    v.z = q4(e + 32, SE);
    v.w = q4(e + 48, SE);
    g_embF[slot] = v;
}

// ------------------------------------------------------------------
// K2: int8 mma GEMM (exact s32 dots of quantized inputs), B via cp.async
// double-buffer. CTA = 64 tokens; warp w: m-tile = w>>1, code-half = w&1.
// Exact fp32 rescore of epsilon-candidates (validated machinery).
// ------------------------------------------------------------------
__global__ void __launch_bounds__(256, 1) k_argmin_mma(const float* __restrict__ emb) {
    extern __shared__ uint4 Bs[];                 // [2][CHUNK_SLOTS] + znS tail
    float* znS = (float*)(Bs + 2 * CHUNK_SLOTS);  // [64]
    const uint32_t BsAddr = smem_u32(Bs);

    const int tid = threadIdx.x;
    const int wid = tid >> 5, lane = tid & 31;
    const int c = lane & 3, g = lane >> 2;
    const int mt = wid >> 1, half = wid & 1;
    const int rowBase = blockIdx.x * MT;
    const int r0 = rowBase + mt * 16 + g;

    // ---- zn (validated sequential fmaf chain) ----
    if (tid < MT) {
        const float4* zr = (const float4*)&g_zf[(rowBase + tid) * EDIM];
        float s = 0.f;
#pragma unroll 8
        for (int i = 0; i < 64; i++) {
            float4 a = zr[i];
            s = fmaf(a.x, a.x, s); s = fmaf(a.y, a.y, s);
            s = fmaf(a.z, a.z, s); s = fmaf(a.w, a.w, s);
        }
        znS[tid] = s;
    }

    // ---- A fragments (int8, z at SZ) into registers: 8 ksteps ----
    uint4 areg[8];
    {
        const float* z0 = &g_zf[r0 * EDIM];
        const float* z1 = &g_zf[(r0 + 8) * EDIM];
#pragma unroll
        for (int ks = 0; ks < 8; ks++) {
            int k = ks * 32 + c * 4;
            areg[ks].x = q4(z0 + k,      SZ);
            areg[ks].y = q4(z1 + k,      SZ);
            areg[ks].z = q4(z0 + k + 16, SZ);
            areg[ks].w = q4(z1 + k + 16, SZ);
        }
    }

    // ---- prefetch chunk 0 ----
#pragma unroll
    for (int it = 0; it < 16; it++) {
        int s = it * 256 + tid;
        cp16(BsAddr + s * 16, &g_embF[s]);
    }
    asm volatile("cp.async.commit_group;" ::: "memory");
    __syncthreads();

    // per-lane token state: h = 0 (row g), 1 (row g+8)
    int bestD[2]; int cnt[2]; float zl[2]; ull cbase[2];
#pragma unroll
    for (int h = 0; h < 2; h++) {
        int t = r0 + h * 8;
        zl[h] = znS[mt * 16 + g + h * 8];
        bestD[h] = BD_INIT;                       // FIX: BD_INIT - EPS_INT stays in int range
        cnt[h] = 0;
        cbase[h] = (ull)(((t * 2 + half) * 4 + c) * CAP);
    }

    const int warpSlotBase = half * 2048;         // 16 ntiles * 4 kp * 32

#pragma unroll 1
    for (int ch = 0; ch < NCH; ch++) {
        const int buf = ch & 1;
        if (ch + 1 < NCH) {
            const uint4* src = &g_embF[(ch + 1) * CHUNK_SLOTS];
            const uint32_t dst = BsAddr + ((ch + 1) & 1) * (CHUNK_SLOTS * 16);
#pragma unroll
            for (int it = 0; it < 16; it++) {
                int s = it * 256 + tid;
                cp16(dst + s * 16, src + s);
            }
            asm volatile("cp.async.commit_group;" ::: "memory");
            asm volatile("cp.async.wait_group 1;" ::: "memory");
        } else {
            asm volatile("cp.async.wait_group 0;" ::: "memory");
        }
        __syncthreads();

        const uint4* Bp = Bs + buf * CHUNK_SLOTS + warpSlotBase + lane;

        int acc[16][4];
#pragma unroll
        for (int j = 0; j < 16; j++)
#pragma unroll
            for (int q = 0; q < 4; q++) acc[j][q] = 0;

#pragma unroll
        for (int kp = 0; kp < 4; kp++) {
            const uint4 a0 = areg[2 * kp], a1 = areg[2 * kp + 1];
#pragma unroll
            for (int j = 0; j < 16; j++) {
                uint4 bf = Bp[(j * 4 + kp) * 32];
                mma_s8(acc[j], a0, bf.x, bf.y);
                mma_s8(acc[j], a1, bf.z, bf.w);
            }
        }
        __syncthreads();    // all warps done reading buf before overwrite

        // epilogue: append candidates with d >= best - EPS_INT
#pragma unroll
        for (int j = 0; j < 16; j++) {
            const int colB = ((ch * 32 + half * 16 + j) * 8) + 2 * c;
#pragma unroll
            for (int q = 0; q < 4; q++) {
                const int h   = q >> 1;
                const int col = colB + (q & 1);
                int d = acc[j][q];
                if (d >= bestD[h] - EPS_INT) {
                    int w = cnt[h] < CAP ? cnt[h] : CAP - 1;
                    g_cand[cbase[h] + w] = ((ull)(uint32_t)d << 32) | (unsigned)col;
                    cnt[h] = w + 1;
                    bestD[h] = d > bestD[h] ? d : bestD[h];
                }
            }
        }
    }

    // ---- filter + exact fp32 rescore + packed atomicMin ----
#pragma unroll 1
    for (int h = 0; h < 2; h++) {
        int bm = bestD[h];
        int o1 = __shfl_xor_sync(0xFFFFFFFF, bm, 1); bm = o1 > bm ? o1 : bm;
        int o2 = __shfl_xor_sync(0xFFFFFFFF, bm, 2); bm = o2 > bm ? o2 : bm;
        const int thr = bm - EPS_INT;
        const int t = r0 + h * 8;
        const float4* zr = (const float4*)&g_zf[t * EDIM];
        ull bp = ~0ULL;
        for (int i = 0; i < cnt[h]; i++) {
            ull e = g_cand[cbase[h] + i];
            int ad = (int)(uint32_t)(e >> 32);
            if (ad < thr) continue;
            int col = (int)(e & 0xFFFFFFFF);
            const float4* er = (const float4*)&emb[col * EDIM];
            float dot = 0.f;
#pragma unroll 8
            for (int k = 0; k < 64; k++) {
                float4 a = zr[k], ev = er[k];
                dot = fmaf(a.x, ev.x, dot); dot = fmaf(a.y, ev.y, dot);
                dot = fmaf(a.z, ev.z, dot); dot = fmaf(a.w, ev.w, dot);
            }
            float sc = fmaf(-2.0f, dot, zl[h]);   // exact reference-order score
            ull pk = ((ull)__float_as_uint(sc) << 32) | (unsigned)col;
            bp = pk < bp ? pk : bp;
        }
        ull o;
        o = __shfl_xor_sync(0xFFFFFFFF, bp, 1); bp = o < bp ? o : bp;
        o = __shfl_xor_sync(0xFFFFFFFF, bp, 2); bp = o < bp ? o : bp;
        if (c == 0) atomicMin(&g_best[t], bp);
    }
}

// ------------------------------------------------------------------
// K3: gather z_q -> NCHW output with reference ST rounding + MSE partials
// ------------------------------------------------------------------
__global__ void k_gather(const float* __restrict__ emb,
                         const float* __restrict__ z,
                         float* __restrict__ out) {
    const int c = blockIdx.x;
    const int b = blockIdx.y;
    const int tid = threadIdx.x;
    float lsum = 0.f;
#pragma unroll
    for (int u = 0; u < 4; u++) {
        int hw = u * 256 + tid;
        int n  = b * HW + hw;
        int k  = (int)(g_best[n] & 0xFFFFFFFF);
        float e  = __ldg(&emb[k * EDIM + c]);
        float zv = z[(b * EDIM + c) * HW + hw];
        float d  = e - zv;
        out[(b * EDIM + c) * HW + hw] = zv + d;
        lsum = fmaf(d, d, lsum);
    }
    __shared__ float red[256];
    red[tid] = lsum;
    __syncthreads();
    for (int s = 128; s > 0; s >>= 1) {
        if (tid < s) red[tid] += red[tid + s];
        __syncthreads();
    }
    if (tid == 0) g_msePart[b * 256 + c] = red[0];
}

// ------------------------------------------------------------------
// K4: losses, idx->float, histogram, perplexity (1024 threads)
// ------------------------------------------------------------------
__global__ void k_finalize(float* __restrict__ out) {
    __shared__ int   counts[NE];
    __shared__ float redf[1024];
    __shared__ float mseS[BATCH];
    const int tid = threadIdx.x;

    for (int i = tid; i < NE; i += 1024) counts[i] = 0;
    __syncthreads();

    for (int i = tid; i < N_TOK; i += 1024) {
        int k = (int)(g_best[i] & 0xFFFFFFFF);
        out[2097160 + i] = (float)k;
        atomicAdd(&counts[k], 1);
    }

    {
        const int b = tid >> 7, i = tid & 127;
        redf[tid] = g_msePart[b * 256 + i] + g_msePart[b * 256 + 128 + i];
        __syncthreads();
        for (int s = 64; s > 0; s >>= 1) {
            if (i < s) redf[tid] += redf[tid + s];
            __syncthreads();
        }
        if (i == 0) mseS[b] = redf[tid];
        __syncthreads();
    }

    if (tid < BATCH) {
        float m = mseS[tid] * (1.0f / 262144.0f);
        out[2097152 + tid] = m + 0.25f * m;
    }
    if (tid == 0) {
        float tot = 0.f;
        for (int b = 0; b < BATCH; b++) tot += mseS[b] * (1.0f / 262144.0f);
        float cm = tot * (1.0f / 8.0f);
        out[2105352] = cm;
        out[2105353] = 0.25f * cm;
    }
    __syncthreads();

    float ps = 0.f;
    for (int i = tid; i < NE; i += 1024) {
        float p = (float)counts[i] * (1.0f / 8192.0f);
        ps += p * logf(p + 1e-10f);
    }
    redf[tid] = ps;
    __syncthreads();
    for (int s = 512; s > 0; s >>= 1) {
        if (tid < s) redf[tid] += redf[tid + s];
        __syncthreads();
    }
    if (tid == 0) out[2105354] = expf(-redf[0]);
}

// ------------------------------------------------------------------
extern "C" void kernel_launch(void* const* d_in, const int* in_sizes, int n_in,
                              void* d_out, int out_size) {
    const float* z   = (const float*)d_in[0];   // [8,256,32,32]
    const float* emb = (const float*)d_in[1];   // [8192,256]
    float* out = (float*)d_out;

    const int smemBytes = 2 * CHUNK_SLOTS * 16 + 256;   // 128KB + znS
    cudaFuncSetAttribute(k_argmin_mma, cudaFuncAttributeMaxDynamicSharedMemorySize, smemBytes);

    dim3 tb(32, 8);
    dim3 tg(HW / 32, EDIM / 32, BATCH);
    k_transpose<<<tg, tb>>>(z);

    k_embfrag<<<(NE / 8 * 4 * 32) / 256, 256>>>(emb);

    k_argmin_mma<<<N_TOK / MT, 256, smemBytes>>>(emb);

    dim3 gg(EDIM, BATCH);
    k_gather<<<gg, 256>>>(emb, z, out);

    k_finalize<<<1, 1024>>>(out);
}

// round 11
// speedup vs baseline: 1.6359x; 1.6359x over previous
#include <cuda_runtime.h>
#include <cuda_fp16.h>
#include <math.h>
#include <stdint.h>

#define N_TOK   8192
#define NE      8192
#define EDIM    256
#define BATCH   8
#define HW      1024

#define MT      64                  // tokens per CTA (4 m16 tiles) -> 128 CTAs
#define KP      8                   // k-pairs (2 x k16 each) covering EDIM=256
#define NCH     64                  // chunks of 128 codes (16 ntiles)
#define SCALE   16384.0f            // 2^14 emb pre-scale for fp16
#define EPS_D   4.5f                // scaled-dot epsilon (input quant + fp16 acc noise)
#define CAP     32

#define CHUNK_SLOTS 4096            // 16 ntiles * KP * 32 lanes (uint4 slots, 64KB)

typedef unsigned long long ull;

// ---- scratch (static device globals; no allocation) ----
__device__ __align__(16) float g_zf[N_TOK * EDIM];        // z [token][dim]
__device__ __align__(16) uint4 g_embF[NE / 8 * KP * 32];  // emb*2^14 fp16 frags (4MB)
__device__ ull   g_cand[N_TOK * 2 * 4 * CAP];             // (dotBits<<32)|idx appends
__device__ ull   g_best[N_TOK];
__device__ float g_msePart[BATCH * 256];

__device__ __forceinline__ uint32_t packh2(float a, float b) {
    __half2 h = __floats2half2_rn(a, b);
    return *reinterpret_cast<uint32_t*>(&h);
}
// fp16-accumulate mma: D,C are 2 regs (half2 x2). Row g in d[0], row g+8 in d[1].
__device__ __forceinline__ void mma_f16acc(uint32_t* d, const uint4& a, uint32_t b0, uint32_t b1) {
    asm("mma.sync.aligned.m16n8k16.row.col.f16.f16.f16.f16 "
        "{%0,%1},{%2,%3,%4,%5},{%6,%7},{%0,%1};"
        : "+r"(d[0]), "+r"(d[1])
        : "r"(a.x), "r"(a.y), "r"(a.z), "r"(a.w), "r"(b0), "r"(b1));
}
__device__ __forceinline__ uint32_t smem_u32(const void* p) {
    uint32_t a;
    asm("{ .reg .u64 t; cvta.to.shared.u64 t, %1; cvt.u32.u64 %0, t; }" : "=r"(a) : "l"(p));
    return a;
}
__device__ __forceinline__ void cp16(uint32_t dst, const void* src) {
    asm volatile("cp.async.cg.shared.global [%0], [%1], 16;" :: "r"(dst), "l"(src) : "memory");
}

// ------------------------------------------------------------------
// K1: NCHW -> [token][dim] transpose  (+ init g_best)
// ------------------------------------------------------------------
__global__ void k_transpose(const float* __restrict__ z) {
    __shared__ float tile[32][33];
    const int b = blockIdx.z;
    const int hwBase = blockIdx.x * 32;
    const int cBase  = blockIdx.y * 32;
    const int tx = threadIdx.x, ty = threadIdx.y;
    const int bid  = (blockIdx.z * gridDim.y + blockIdx.y) * gridDim.x + blockIdx.x;
    const int tlin = bid * 256 + ty * 32 + tx;
    if (tlin < N_TOK) g_best[tlin] = ~0ULL;
#pragma unroll
    for (int j = 0; j < 4; j++) {
        int c = cBase + ty + 8 * j;
        tile[ty + 8 * j][tx] = z[(b * EDIM + c) * HW + hwBase + tx];
    }
    __syncthreads();
#pragma unroll
    for (int j = 0; j < 4; j++) {
        int hw = hwBase + ty + 8 * j;
        g_zf[(b * HW + hw) * EDIM + cBase + tx] = tile[tx][ty + 8 * j];
    }
}

// ------------------------------------------------------------------
// K1b: emb -> scaled fp16 fragment layout (m16n8k16 B frags).
// slot = (ntile*KP + kp)*32 + lane
// ------------------------------------------------------------------
__global__ void k_embfrag(const float* __restrict__ emb) {
    int slot = blockIdx.x * 256 + threadIdx.x;
    int lane  = slot & 31;
    int kp    = (slot >> 5) & (KP - 1);
    int ntile = slot >> 8;
    int n  = ntile * 8 + (lane >> 2);
    int kb = kp * 32 + (lane & 3) * 2;
    const float* e = emb + n * EDIM + kb;
    uint4 v;
    v.x = packh2(__ldg(e)      * SCALE, __ldg(e + 1)  * SCALE);
    v.y = packh2(__ldg(e + 8)  * SCALE, __ldg(e + 9)  * SCALE);
    v.z = packh2(__ldg(e + 16) * SCALE, __ldg(e + 17) * SCALE);
    v.w = packh2(__ldg(e + 24) * SCALE, __ldg(e + 25) * SCALE);
    g_embF[slot] = v;
}

// ------------------------------------------------------------------
// K2: fp16 mma (fp16 accumulators), B staged via cp.async double-buffer.
// CTA = 64 tokens; warp w: m-tile = w>>1, code-half = w&1.
// Rank by max scaled dot; exact fp32 rescore of epsilon-candidates.
// ------------------------------------------------------------------
__global__ void __launch_bounds__(256, 1) k_argmin_mma(const float* __restrict__ emb) {
    extern __shared__ uint4 Bs[];                 // [2][CHUNK_SLOTS] + znS tail
    float* znS = (float*)(Bs + 2 * CHUNK_SLOTS);  // [64]
    const uint32_t BsAddr = smem_u32(Bs);

    const int tid = threadIdx.x;
    const int wid = tid >> 5, lane = tid & 31;
    const int c = lane & 3, g = lane >> 2;
    const int mt = wid >> 1, half = wid & 1;
    const int rowBase = blockIdx.x * MT;
    const int r0 = rowBase + mt * 16 + g;

    // ---- zn (validated sequential fmaf chain) ----
    if (tid < MT) {
        const float4* zr = (const float4*)&g_zf[(rowBase + tid) * EDIM];
        float s = 0.f;
#pragma unroll 8
        for (int i = 0; i < 64; i++) {
            float4 a = zr[i];
            s = fmaf(a.x, a.x, s); s = fmaf(a.y, a.y, s);
            s = fmaf(a.z, a.z, s); s = fmaf(a.w, a.w, s);
        }
        znS[tid] = s;
    }

    // ---- A fragments into registers (fp16, unscaled z) ----
    uint4 areg[16];
    {
        const float* z0 = &g_zf[r0 * EDIM];
        const float* z1 = &g_zf[(r0 + 8) * EDIM];
#pragma unroll
        for (int ks = 0; ks < 16; ks++) {
            int k = ks * 16 + c * 2;
            float2 a0 = *(const float2*)(z0 + k);
            float2 a1 = *(const float2*)(z1 + k);
            float2 b0 = *(const float2*)(z0 + k + 8);
            float2 b1 = *(const float2*)(z1 + k + 8);
            areg[ks].x = packh2(a0.x, a0.y);
            areg[ks].y = packh2(a1.x, a1.y);
            areg[ks].z = packh2(b0.x, b0.y);
            areg[ks].w = packh2(b1.x, b1.y);
        }
    }

    // ---- prefetch chunk 0 ----
#pragma unroll
    for (int it = 0; it < 16; it++) {
        int s = it * 256 + tid;
        cp16(BsAddr + s * 16, &g_embF[s]);
    }
    asm volatile("cp.async.commit_group;" ::: "memory");
    __syncthreads();

    // per-lane token state: h = 0 (row g), 1 (row g+8)
    float bestD[2]; int cnt[2]; float zl[2]; ull cbase[2];
#pragma unroll
    for (int h = 0; h < 2; h++) {
        int t = r0 + h * 8;
        zl[h] = znS[mt * 16 + g + h * 8];
        bestD[h] = -__int_as_float(0x7f800000);
        cnt[h] = 0;
        cbase[h] = (ull)(((t * 2 + half) * 4 + c) * CAP);
    }

    const int ntlBase = half * 8;

#pragma unroll 1
    for (int ch = 0; ch < NCH; ch++) {
        const int buf = ch & 1;
        if (ch + 1 < NCH) {
            const uint4* src = &g_embF[(ch + 1) * CHUNK_SLOTS];
            const uint32_t dst = BsAddr + ((ch + 1) & 1) * (CHUNK_SLOTS * 16);
#pragma unroll
            for (int it = 0; it < 16; it++) {
                int s = it * 256 + tid;
                cp16(dst + s * 16, src + s);
            }
            asm volatile("cp.async.commit_group;" ::: "memory");
            asm volatile("cp.async.wait_group 1;" ::: "memory");
        } else {
            asm volatile("cp.async.wait_group 0;" ::: "memory");
        }
        __syncthreads();

        const uint4* Bp = Bs + buf * CHUNK_SLOTS + (ntlBase * 8) * 32 + lane;

        uint32_t acc[8][2];                       // half2 accumulators (zeros)
#pragma unroll
        for (int j = 0; j < 8; j++) { acc[j][0] = 0u; acc[j][1] = 0u; }

#pragma unroll
        for (int kp = 0; kp < KP; kp++) {
            const uint4 a0 = areg[2 * kp], a1 = areg[2 * kp + 1];
#pragma unroll
            for (int j = 0; j < 8; j++) {
                uint4 bf = Bp[(j * 8 + kp) * 32];
                mma_f16acc(acc[j], a0, bf.x, bf.y);
                mma_f16acc(acc[j], a1, bf.z, bf.w);
            }
        }
        __syncthreads();    // done reading buf before overwrite (ch+2)

        // epilogue: unpack half2 dots, append candidates >= best - EPS_D
#pragma unroll
        for (int j = 0; j < 8; j++) {
            const int colB = (ch * 16 + ntlBase + j) * 8 + 2 * c;
#pragma unroll
            for (int h = 0; h < 2; h++) {
                __half2 dv = *reinterpret_cast<__half2*>(&acc[j][h]);
                float dlo = __low2float(dv), dhi = __high2float(dv);
                if (dlo >= bestD[h] - EPS_D) {
                    int w = cnt[h] < CAP ? cnt[h] : CAP - 1;
                    g_cand[cbase[h] + w] = ((ull)__float_as_uint(dlo) << 32) | (unsigned)colB;
                    cnt[h] = w + 1;
                    bestD[h] = fmaxf(bestD[h], dlo);
                }
                if (dhi >= bestD[h] - EPS_D) {
                    int w = cnt[h] < CAP ? cnt[h] : CAP - 1;
                    g_cand[cbase[h] + w] = ((ull)__float_as_uint(dhi) << 32) | (unsigned)(colB + 1);
                    cnt[h] = w + 1;
                    bestD[h] = fmaxf(bestD[h], dhi);
                }
            }
        }
    }

    // ---- filter + exact fp32 rescore + packed atomicMin ----
#pragma unroll 1
    for (int h = 0; h < 2; h++) {
        float bm = bestD[h];
        bm = fmaxf(bm, __shfl_xor_sync(0xFFFFFFFF, bm, 1));
        bm = fmaxf(bm, __shfl_xor_sync(0xFFFFFFFF, bm, 2));
        const float thr = bm - EPS_D;
        const int t = r0 + h * 8;
        const float4* zr = (const float4*)&g_zf[t * EDIM];
        ull bp = ~0ULL;
        for (int i = 0; i < cnt[h]; i++) {
            ull e = g_cand[cbase[h] + i];
            float ad = __uint_as_float((uint32_t)(e >> 32));
            if (ad < thr) continue;
            int col = (int)(e & 0xFFFFFFFF);
            const float4* er = (const float4*)&emb[col * EDIM];
            float dot = 0.f;
#pragma unroll 8
            for (int k = 0; k < 64; k++) {
                float4 a = zr[k], ev = er[k];
                dot = fmaf(a.x, ev.x, dot); dot = fmaf(a.y, ev.y, dot);
                dot = fmaf(a.z, ev.z, dot); dot = fmaf(a.w, ev.w, dot);
            }
            float sc = fmaf(-2.0f, dot, zl[h]);   // exact reference-order score
            ull pk = ((ull)__float_as_uint(sc) << 32) | (unsigned)col;
            bp = pk < bp ? pk : bp;
        }
        ull o;
        o = __shfl_xor_sync(0xFFFFFFFF, bp, 1); bp = o < bp ? o : bp;
        o = __shfl_xor_sync(0xFFFFFFFF, bp, 2); bp = o < bp ? o : bp;
        if (c == 0) atomicMin(&g_best[t], bp);
    }
}

// ------------------------------------------------------------------
// K3: gather z_q -> NCHW output with reference ST rounding + MSE partials
// ------------------------------------------------------------------
__global__ void k_gather(const float* __restrict__ emb,
                         const float* __restrict__ z,
                         float* __restrict__ out) {
    const int c = blockIdx.x;
    const int b = blockIdx.y;
    const int tid = threadIdx.x;
    float lsum = 0.f;
#pragma unroll
    for (int u = 0; u < 4; u++) {
        int hw = u * 256 + tid;
        int n  = b * HW + hw;
        int k  = (int)(g_best[n] & 0xFFFFFFFF);
        float e  = __ldg(&emb[k * EDIM + c]);
        float zv = z[(b * EDIM + c) * HW + hw];
        float d  = e - zv;
        out[(b * EDIM + c) * HW + hw] = zv + d;
        lsum = fmaf(d, d, lsum);
    }
    __shared__ float red[256];
    red[tid] = lsum;
    __syncthreads();
    for (int s = 128; s > 0; s >>= 1) {
        if (tid < s) red[tid] += red[tid + s];
        __syncthreads();
    }
    if (tid == 0) g_msePart[b * 256 + c] = red[0];
}

// ------------------------------------------------------------------
// K4: losses, idx->float, histogram, perplexity (1024 threads)
// ------------------------------------------------------------------
__global__ void k_finalize(float* __restrict__ out) {
    __shared__ int   counts[NE];
    __shared__ float redf[1024];
    __shared__ float mseS[BATCH];
    const int tid = threadIdx.x;

    for (int i = tid; i < NE; i += 1024) counts[i] = 0;
    __syncthreads();

    for (int i = tid; i < N_TOK; i += 1024) {
        int k = (int)(g_best[i] & 0xFFFFFFFF);
        out[2097160 + i] = (float)k;
        atomicAdd(&counts[k], 1);
    }

    {
        const int b = tid >> 7, i = tid & 127;
        redf[tid] = g_msePart[b * 256 + i] + g_msePart[b * 256 + 128 + i];
        __syncthreads();
        for (int s = 64; s > 0; s >>= 1) {
            if (i < s) redf[tid] += redf[tid + s];
            __syncthreads();
        }
        if (i == 0) mseS[b] = redf[tid];
        __syncthreads();
    }

    if (tid < BATCH) {
        float m = mseS[tid] * (1.0f / 262144.0f);
        out[2097152 + tid] = m + 0.25f * m;
    }
    if (tid == 0) {
        float tot = 0.f;
        for (int b = 0; b < BATCH; b++) tot += mseS[b] * (1.0f / 262144.0f);
        float cm = tot * (1.0f / 8.0f);
        out[2105352] = cm;
        out[2105353] = 0.25f * cm;
    }
    __syncthreads();

    float ps = 0.f;
    for (int i = tid; i < NE; i += 1024) {
        float p = (float)counts[i] * (1.0f / 8192.0f);
        ps += p * logf(p + 1e-10f);
    }
    redf[tid] = ps;
    __syncthreads();
    for (int s = 512; s > 0; s >>= 1) {
        if (tid < s) redf[tid] += redf[tid + s];
        __syncthreads();
    }
    if (tid == 0) out[2105354] = expf(-redf[0]);
}

// ------------------------------------------------------------------
extern "C" void kernel_launch(void* const* d_in, const int* in_sizes, int n_in,
                              void* d_out, int out_size) {
    const float* z   = (const float*)d_in[0];   // [8,256,32,32]
    const float* emb = (const float*)d_in[1];   // [8192,256]
    float* out = (float*)d_out;

    const int smemBytes = 2 * CHUNK_SLOTS * 16 + 256;   // 128KB + znS
    cudaFuncSetAttribute(k_argmin_mma, cudaFuncAttributeMaxDynamicSharedMemorySize, smemBytes);

    dim3 tb(32, 8);
    dim3 tg(HW / 32, EDIM / 32, BATCH);
    k_transpose<<<tg, tb>>>(z);

    k_embfrag<<<(NE / 8 * KP * 32) / 256, 256>>>(emb);

    k_argmin_mma<<<N_TOK / MT, 256, smemBytes>>>(emb);

    dim3 gg(EDIM, BATCH);
    k_gather<<<gg, 256>>>(emb, z, out);

    k_finalize<<<1, 1024>>>(out);
}

// round 13
// speedup vs baseline: 1.7708x; 1.0824x over previous
#include <cuda_runtime.h>
#include <cuda_fp16.h>
#include <math.h>
#include <stdint.h>

#define N_TOK   8192
#define NE      8192
#define EDIM    256
#define BATCH   8
#define HW      1024

#define MT      64                  // tokens per CTA (4 m16 tiles) -> 128 CTAs
#define KP      8                   // k-pairs (2 x k16 each) covering EDIM=256
#define NCH     64                  // chunks of 128 codes (16 ntiles)
#define SCALE   16384.0f            // 2^14 emb pre-scale for fp16
#define EPS_D   3.0f                // scaled-dot epsilon (1.8e-4 unscaled)
#define CAP     32

#define CHUNK_SLOTS 4096            // 16 ntiles * KP * 32 lanes (uint4 slots, 64KB)
#define EMBF_SLOTS  (NE / 8 * KP * 32)   // 262144 uint4 slots
#define TRANS_BLKS  2048
#define EMBF_BLKS   (EMBF_SLOTS / 256)   // 1024

typedef unsigned long long ull;

// ---- scratch (static device globals; no allocation) ----
__device__ __align__(16) float g_zf[N_TOK * EDIM];        // z [token][dim]
__device__ __align__(16) uint4 g_embF[EMBF_SLOTS];        // emb*2^14 fp16 frags (4MB)
__device__ ull   g_cand[N_TOK * 2 * 4 * CAP];             // (dotBits<<32)|idx appends
__device__ ull   g_best[N_TOK];
__device__ float g_msePart[BATCH * 256];

__device__ __forceinline__ uint32_t packh2(float a, float b) {
    __half2 h = __floats2half2_rn(a, b);
    return *reinterpret_cast<uint32_t*>(&h);
}
__device__ __forceinline__ void mma_f16(float* d, const uint4& a, uint32_t b0, uint32_t b1) {
    asm("mma.sync.aligned.m16n8k16.row.col.f32.f16.f16.f32 "
        "{%0,%1,%2,%3},{%4,%5,%6,%7},{%8,%9},{%0,%1,%2,%3};"
        : "+f"(d[0]), "+f"(d[1]), "+f"(d[2]), "+f"(d[3])
        : "r"(a.x), "r"(a.y), "r"(a.z), "r"(a.w), "r"(b0), "r"(b1));
}
__device__ __forceinline__ uint32_t smem_u32(const void* p) {
    uint32_t a;
    asm("{ .reg .u64 t; cvta.to.shared.u64 t, %1; cvt.u32.u64 %0, t; }" : "=r"(a) : "l"(p));
    return a;
}
__device__ __forceinline__ void cp16(uint32_t dst, const void* src) {
    asm volatile("cp.async.cg.shared.global [%0], [%1], 16;" :: "r"(dst), "l"(src) : "memory");
}

// ------------------------------------------------------------------
// K1 (fused prep): blocks [0,2048): NCHW->token-major transpose (+g_best init)
//                  blocks [2048,3072): emb -> scaled fp16 fragment layout
// ------------------------------------------------------------------
__global__ void k_prep(const float* __restrict__ z, const float* __restrict__ emb) {
    const int bid = blockIdx.x;
    const int tid = threadIdx.x;
    if (bid < TRANS_BLKS) {
        __shared__ float tile[32][33];
        const int b = bid >> 8;
        const int cBase  = ((bid >> 5) & 7) * 32;
        const int hwBase = (bid & 31) * 32;
        const int tx = tid & 31, ty = tid >> 5;     // 32 x 8
        const int tlin = bid * 256 + tid;
        if (tlin < N_TOK) g_best[tlin] = ~0ULL;
#pragma unroll
        for (int j = 0; j < 4; j++) {
            int c = cBase + ty + 8 * j;
            tile[ty + 8 * j][tx] = z[(b * EDIM + c) * HW + hwBase + tx];
        }
        __syncthreads();
#pragma unroll
        for (int j = 0; j < 4; j++) {
            int hw = hwBase + ty + 8 * j;
            g_zf[(b * HW + hw) * EDIM + cBase + tx] = tile[tx][ty + 8 * j];
        }
    } else {
        // embfrag: slot = (ntile*KP + kp)*32 + lane, covers all 262144 slots
        int slot = (bid - TRANS_BLKS) * 256 + tid;
        int lane  = slot & 31;
        int kp    = (slot >> 5) & (KP - 1);
        int ntile = slot >> 8;
        int n  = ntile * 8 + (lane >> 2);
        int kb = kp * 32 + (lane & 3) * 2;
        const float* e = emb + n * EDIM + kb;
        uint4 v;
        v.x = packh2(__ldg(e)      * SCALE, __ldg(e + 1)  * SCALE);
        v.y = packh2(__ldg(e + 8)  * SCALE, __ldg(e + 9)  * SCALE);
        v.z = packh2(__ldg(e + 16) * SCALE, __ldg(e + 17) * SCALE);
        v.w = packh2(__ldg(e + 24) * SCALE, __ldg(e + 25) * SCALE);
        g_embF[slot] = v;
    }
}

// ------------------------------------------------------------------
// K2: fp16 mma GEMM (f32 acc), B staged through smem via cp.async
// double-buffer. CTA = 64 tokens; warp w: m-tile = w>>1, code-half = w&1.
// (R8 kernel verbatim — measured legacy-mma floor.)
// ------------------------------------------------------------------
__global__ void __launch_bounds__(256, 1) k_argmin_mma(const float* __restrict__ emb) {
    extern __shared__ uint4 Bs[];                 // [2][CHUNK_SLOTS] + znS tail
    float* znS = (float*)(Bs + 2 * CHUNK_SLOTS);  // [64]
    const uint32_t BsAddr = smem_u32(Bs);

    const int tid = threadIdx.x;
    const int wid = tid >> 5, lane = tid & 31;
    const int c = lane & 3, g = lane >> 2;
    const int mt = wid >> 1, half = wid & 1;
    const int rowBase = blockIdx.x * MT;
    const int r0 = rowBase + mt * 16 + g;

    // ---- zn (validated sequential fmaf chain) ----
    if (tid < MT) {
        const float4* zr = (const float4*)&g_zf[(rowBase + tid) * EDIM];
        float s = 0.f;
#pragma unroll 8
        for (int i = 0; i < 64; i++) {
            float4 a = zr[i];
            s = fmaf(a.x, a.x, s); s = fmaf(a.y, a.y, s);
            s = fmaf(a.z, a.z, s); s = fmaf(a.w, a.w, s);
        }
        znS[tid] = s;
    }

    // ---- A fragments into registers (fp16, unscaled z) ----
    uint4 areg[16];
    {
        const float* z0 = &g_zf[r0 * EDIM];
        const float* z1 = &g_zf[(r0 + 8) * EDIM];
#pragma unroll
        for (int ks = 0; ks < 16; ks++) {
            int k = ks * 16 + c * 2;
            float2 a0 = *(const float2*)(z0 + k);
            float2 a1 = *(const float2*)(z1 + k);
            float2 b0 = *(const float2*)(z0 + k + 8);
            float2 b1 = *(const float2*)(z1 + k + 8);
            areg[ks].x = packh2(a0.x, a0.y);
            areg[ks].y = packh2(a1.x, a1.y);
            areg[ks].z = packh2(b0.x, b0.y);
            areg[ks].w = packh2(b1.x, b1.y);
        }
    }

    // ---- prefetch chunk 0 ----
#pragma unroll
    for (int it = 0; it < 16; it++) {
        int s = it * 256 + tid;
        cp16(BsAddr + s * 16, &g_embF[s]);
    }
    asm volatile("cp.async.commit_group;" ::: "memory");
    __syncthreads();

    // per-lane token state: h = 0 (row g), 1 (row g+8)
    float bestD[2]; int cnt[2]; float zl[2]; ull cbase[2];
#pragma unroll
    for (int h = 0; h < 2; h++) {
        int t = r0 + h * 8;
        zl[h] = znS[mt * 16 + g + h * 8];
        bestD[h] = -__int_as_float(0x7f800000);
        cnt[h] = 0;
        cbase[h] = (ull)(((t * 2 + half) * 4 + c) * CAP);
    }

    const int ntlBase = half * 8;

#pragma unroll 1
    for (int ch = 0; ch < NCH; ch++) {
        const int buf = ch & 1;
        if (ch + 1 < NCH) {
            const uint4* src = &g_embF[(ch + 1) * CHUNK_SLOTS];
            const uint32_t dst = BsAddr + ((ch + 1) & 1) * (CHUNK_SLOTS * 16);
#pragma unroll
            for (int it = 0; it < 16; it++) {
                int s = it * 256 + tid;
                cp16(dst + s * 16, src + s);
            }
            asm volatile("cp.async.commit_group;" ::: "memory");
            asm volatile("cp.async.wait_group 1;" ::: "memory");
        } else {
            asm volatile("cp.async.wait_group 0;" ::: "memory");
        }
        __syncthreads();

        const uint4* Bp = Bs + buf * CHUNK_SLOTS + (ntlBase * 8) * 32 + lane;

        float acc[8][4];
#pragma unroll
        for (int j = 0; j < 8; j++)
#pragma unroll
            for (int q = 0; q < 4; q++) acc[j][q] = 0.f;

#pragma unroll
        for (int kp = 0; kp < KP; kp++) {
            const uint4 a0 = areg[2 * kp], a1 = areg[2 * kp + 1];
#pragma unroll
            for (int j = 0; j < 8; j++) {
                uint4 bf = Bp[(j * 8 + kp) * 32];
                mma_f16(acc[j], a0, bf.x, bf.y);
                mma_f16(acc[j], a1, bf.z, bf.w);
            }
        }
        __syncthreads();    // done reading buf before overwrite (ch+2)

        // epilogue: append candidates >= best - EPS_D (ascending code order)
#pragma unroll
        for (int j = 0; j < 8; j++) {
            const int colB = (ch * 16 + ntlBase + j) * 8 + 2 * c;
#pragma unroll
            for (int q = 0; q < 4; q++) {
                const int h   = q >> 1;
                const int col = colB + (q & 1);
                float d = acc[j][q];
                if (d >= bestD[h] - EPS_D) {
                    int w = cnt[h] < CAP ? cnt[h] : CAP - 1;
                    g_cand[cbase[h] + w] = ((ull)__float_as_uint(d) << 32) | (unsigned)col;
                    cnt[h] = w + 1;
                    bestD[h] = fmaxf(bestD[h], d);
                }
            }
        }
    }

    // ---- filter + exact fp32 rescore + packed atomicMin ----
#pragma unroll 1
    for (int h = 0; h < 2; h++) {
        float bm = bestD[h];
        bm = fmaxf(bm, __shfl_xor_sync(0xFFFFFFFF, bm, 1));
        bm = fmaxf(bm, __shfl_xor_sync(0xFFFFFFFF, bm, 2));
        const float thr = bm - EPS_D;
        const int t = r0 + h * 8;
        const float4* zr = (const float4*)&g_zf[t * EDIM];
        ull bp = ~0ULL;
        for (int i = 0; i < cnt[h]; i++) {
            ull e = g_cand[cbase[h] + i];
            float ad = __uint_as_float((uint32_t)(e >> 32));
            if (ad < thr) continue;
            int col = (int)(e & 0xFFFFFFFF);
            const float4* er = (const float4*)&emb[col * EDIM];
            float dot = 0.f;
#pragma unroll 8
            for (int k = 0; k < 64; k++) {
                float4 a = zr[k], ev = er[k];
                dot = fmaf(a.x, ev.x, dot); dot = fmaf(a.y, ev.y, dot);
                dot = fmaf(a.z, ev.z, dot); dot = fmaf(a.w, ev.w, dot);
            }
            float sc = fmaf(-2.0f, dot, zl[h]);   // exact reference-order score
            ull pk = ((ull)__float_as_uint(sc) << 32) | (unsigned)col;
            bp = pk < bp ? pk : bp;
        }
        ull o;
        o = __shfl_xor_sync(0xFFFFFFFF, bp, 1); bp = o < bp ? o : bp;
        o = __shfl_xor_sync(0xFFFFFFFF, bp, 2); bp = o < bp ? o : bp;
        if (c == 0) atomicMin(&g_best[t], bp);
    }
}

// ------------------------------------------------------------------
// K3: gather z_q -> NCHW output (ST rounding) + MSE partials.
// Block = (channel-quad, batch): one float4 emb read per (token, 4 channels).
// ------------------------------------------------------------------
__global__ void k_gather(const float* __restrict__ emb,
                         const float* __restrict__ z,
                         float* __restrict__ out) {
    const int cq = blockIdx.x;           // 0..63 (channel quad)
    const int b  = blockIdx.y;
    const int tid = threadIdx.x;
    float lsum[4] = {0.f, 0.f, 0.f, 0.f};
#pragma unroll
    for (int u = 0; u < 4; u++) {
        int hw = u * 256 + tid;
        int n  = b * HW + hw;
        int k  = (int)(g_best[n] & 0xFFFFFFFF);
        float4 e4 = __ldg((const float4*)&emb[k * EDIM + cq * 4]);
        float ev[4] = {e4.x, e4.y, e4.z, e4.w};
#pragma unroll
        for (int p = 0; p < 4; p++) {
            int cc = cq * 4 + p;
            float zv = z[(b * EDIM + cc) * HW + hw];
            float d  = ev[p] - zv;
            out[(b * EDIM + cc) * HW + hw] = zv + d;   // straight-through rounding
            lsum[p] = fmaf(d, d, lsum[p]);
        }
    }
    __shared__ float red[256];
#pragma unroll
    for (int p = 0; p < 4; p++) {
        red[tid] = lsum[p];
        __syncthreads();
        for (int s = 128; s > 0; s >>= 1) {
            if (tid < s) red[tid] += red[tid + s];
            __syncthreads();
        }
        if (tid == 0) g_msePart[b * 256 + cq * 4 + p] = red[0];
        __syncthreads();
    }
}

// ------------------------------------------------------------------
// K4: losses, idx->float, histogram, perplexity (1024 threads)
// ------------------------------------------------------------------
__global__ void k_finalize(float* __restrict__ out) {
    __shared__ int   counts[NE];
    __shared__ float redf[1024];
    __shared__ float mseS[BATCH];
    const int tid = threadIdx.x;

    for (int i = tid; i < NE; i += 1024) counts[i] = 0;
    __syncthreads();

    for (int i = tid; i < N_TOK; i += 1024) {
        int k = (int)(g_best[i] & 0xFFFFFFFF);
        out[2097160 + i] = (float)k;
        atomicAdd(&counts[k], 1);
    }

    {
        const int b = tid >> 7, i = tid & 127;
        redf[tid] = g_msePart[b * 256 + i] + g_msePart[b * 256 + 128 + i];
        __syncthreads();
        for (int s = 64; s > 0; s >>= 1) {
            if (i < s) redf[tid] += redf[tid + s];
            __syncthreads();
        }
        if (i == 0) mseS[b] = redf[tid];
        __syncthreads();
    }

    if (tid < BATCH) {
        float m = mseS[tid] * (1.0f / 262144.0f);
        out[2097152 + tid] = m + 0.25f * m;
    }
    if (tid == 0) {
        float tot = 0.f;
        for (int b = 0; b < BATCH; b++) tot += mseS[b] * (1.0f / 262144.0f);
        float cm = tot * (1.0f / 8.0f);
        out[2105352] = cm;
        out[2105353] = 0.25f * cm;
    }
    __syncthreads();

    float ps = 0.f;
    for (int i = tid; i < NE; i += 1024) {
        float p = (float)counts[i] * (1.0f / 8192.0f);
        ps += p * logf(p + 1e-10f);
    }
    redf[tid] = ps;
    __syncthreads();
    for (int s = 512; s > 0; s >>= 1) {
        if (tid < s) redf[tid] += redf[tid + s];
        __syncthreads();
    }
    if (tid == 0) out[2105354] = expf(-redf[0]);
}

// ------------------------------------------------------------------
extern "C" void kernel_launch(void* const* d_in, const int* in_sizes, int n_in,
                              void* d_out, int out_size) {
    const float* z   = (const float*)d_in[0];   // [8,256,32,32]
    const float* emb = (const float*)d_in[1];   // [8192,256]
    float* out = (float*)d_out;

    const int smemBytes = 2 * CHUNK_SLOTS * 16 + 256;   // 128KB + znS
    cudaFuncSetAttribute(k_argmin_mma, cudaFuncAttributeMaxDynamicSharedMemorySize, smemBytes);

    k_prep<<<TRANS_BLKS + EMBF_BLKS, 256>>>(z, emb);     // 3072 blocks (fix)

    k_argmin_mma<<<N_TOK / MT, 256, smemBytes>>>(emb);

    dim3 gg(EDIM / 4, BATCH);
    k_gather<<<gg, 256>>>(emb, z, out);

    k_finalize<<<1, 1024>>>(out);
}